// round 15
// baseline (speedup 1.0000x reference)
#include <cuda_runtime.h>
#include <cuda_fp16.h>
#include <cstdint>
#include <math.h>

#define S_LEN   2048
#define D_IN    4096
#define D_OUTD  4096
#define M_TOK   8192
#define RK      16
#define ER      64
#define ER2     128         // padded LoRA K
#define SCALING 2.0f

// ---- main fp16 mma gemm config: CTA 128x256, 8 warps, warp 64x64, BK=128, 2 stages ----
#define BM      128
#define BN      256
#define BK      128
#define STAGES  2
#define NIT_TOT 33                       // 4096/128 main + 1 padded lora chunk
#define A_BYTES (BM*BK*2)                // 32768
#define B_BYTES (BN*BK*2)                // 65536
#define STAGE_BYTES (A_BYTES + B_BYTES)  // 98304
#define SMEM_TOTAL (STAGES*STAGE_BYTES)  // 196608

// ---------------- scratch (half copies) ----------------
__device__ __align__(1024) __half g_xh[M_TOK * D_IN];     // 67 MB
__device__ __align__(1024) __half g_wh[D_OUTD * D_IN];    // 33.5 MB
__device__ __align__(1024) __half g_lah[ER * D_IN];       // lora_A half [er][k]
__device__ __align__(1024) __half g_ch[M_TOK * ER2];      // gate-scaled h, K-padded (cols 64..127 stay 0)
__device__ __align__(1024) __half g_lbth[D_OUTD * ER2];   // lora_B re-laid [o][er], K-padded
__device__ float g_gate[M_TOK * 4];

// ---------------- helpers ----------------
static __device__ __forceinline__ uint32_t smem_u32(const void* p) {
    uint32_t a;
    asm("{ .reg .u64 t; cvta.to.shared.u64 t, %1; cvt.u32.u64 %0, t; }" : "=r"(a) : "l"(p));
    return a;
}
#define CP_ASYNC16(dst, src) \
    asm volatile("cp.async.cg.shared.global [%0], [%1], 16;" :: "r"(dst), "l"(src) : "memory")
#define CP_COMMIT() asm volatile("cp.async.commit_group;" ::: "memory")
#define CP_WAIT0()  asm volatile("cp.async.wait_group 0;" ::: "memory")
#define CP_WAIT1()  asm volatile("cp.async.wait_group 1;" ::: "memory")

#define LDSM4(r0, r1, r2, r3, a) \
    asm volatile("ldmatrix.sync.aligned.m8n8.x4.shared.b16 {%0,%1,%2,%3}, [%4];" \
        : "=r"(r0), "=r"(r1), "=r"(r2), "=r"(r3) : "r"(a))

#define MMA16816(c0, c1, c2, c3, a0, a1, a2, a3, b0, b1) \
    asm volatile("mma.sync.aligned.m16n8k16.row.col.f32.f16.f16.f32 " \
        "{%0,%1,%2,%3}, {%4,%5,%6,%7}, {%8,%9}, {%0,%1,%2,%3};" \
        : "+f"(c0), "+f"(c1), "+f"(c2), "+f"(c3) \
        : "r"(a0), "r"(a1), "r"(a2), "r"(a3), "r"(b0), "r"(b1))

// ======== prep1: conv_xg (0..1023) || conv_small (1024..1151) || conv_w (1152..2175) ========
__global__ __launch_bounds__(256) void prep1(
    const float* __restrict__ x,
    const float* __restrict__ w_img, const float* __restrict__ b_img,
    const float* __restrict__ w_txt, const float* __restrict__ b_txt,
    const float* __restrict__ lora_A, const float* __restrict__ lora_B,
    const float* __restrict__ w_base)
{
    int bid = blockIdx.x;
    if (bid < 1024) {
        // ---- conv_x + router gate: one warp per token, 4-deep x prefetch pipeline ----
        int warp = threadIdx.x >> 5, lane = threadIdx.x & 31;
        int t = bid * 8 + warp;
        int s = t & (S_LEN - 1);
        const float* wr = (s < 32) ? w_img : w_txt;
        const float* br = (s < 32) ? b_img : b_txt;
        const float* xp = x + (size_t)t * D_IN + lane * 4;
        __half* xh = g_xh + (size_t)t * D_IN + lane * 4;
        const float* wp = wr + lane * 4;

        float a0 = 0.f, a1 = 0.f, a2 = 0.f, a3 = 0.f;

        float4 xv[4];
        #pragma unroll
        for (int p = 0; p < 4; p++)
            xv[p] = *(const float4*)(xp + p * 128);

        #pragma unroll 4
        for (int itc = 0; itc < 32; itc++) {
            float4 v = xv[itc & 3];
            if (itc + 4 < 32)
                xv[itc & 3] = *(const float4*)(xp + (itc + 4) * 128);

            int k = itc * 128;
            __half2 h[2];
            h[0] = __floats2half2_rn(v.x, v.y);
            h[1] = __floats2half2_rn(v.z, v.w);
            *(uint2*)(xh + k) = *(uint2*)h;

            float4 w0 = *(const float4*)(wp + k);
            float4 w1 = *(const float4*)(wp + D_IN + k);
            float4 w2 = *(const float4*)(wp + 2 * D_IN + k);
            float4 w3 = *(const float4*)(wp + 3 * D_IN + k);
            a0 = fmaf(v.x, w0.x, fmaf(v.y, w0.y, fmaf(v.z, w0.z, fmaf(v.w, w0.w, a0))));
            a1 = fmaf(v.x, w1.x, fmaf(v.y, w1.y, fmaf(v.z, w1.z, fmaf(v.w, w1.w, a1))));
            a2 = fmaf(v.x, w2.x, fmaf(v.y, w2.y, fmaf(v.z, w2.z, fmaf(v.w, w2.w, a2))));
            a3 = fmaf(v.x, w3.x, fmaf(v.y, w3.y, fmaf(v.z, w3.z, fmaf(v.w, w3.w, a3))));
        }
        #pragma unroll
        for (int off = 16; off; off >>= 1) {
            a0 += __shfl_down_sync(0xffffffffu, a0, off);
            a1 += __shfl_down_sync(0xffffffffu, a1, off);
            a2 += __shfl_down_sync(0xffffffffu, a2, off);
            a3 += __shfl_down_sync(0xffffffffu, a3, off);
        }
        if (lane == 0) {
            float l0 = a0 + br[0], l1 = a1 + br[1], l2 = a2 + br[2], l3 = a3 + br[3];
            float mx = fmaxf(fmaxf(l0, l1), fmaxf(l2, l3));
            float e0 = expf(l0 - mx), e1 = expf(l1 - mx), e2 = expf(l2 - mx), e3 = expf(l3 - mx);
            float inv = 1.0f / (e0 + e1 + e2 + e3);
            g_gate[t * 4 + 0] = e0 * inv; g_gate[t * 4 + 1] = e1 * inv;
            g_gate[t * 4 + 2] = e2 * inv; g_gate[t * 4 + 3] = e3 * inv;
        }
    } else if (bid < 1152) {
        // ---- conv_small: lora_A -> half, lora_B -> transposed padded half ----
        for (int i = (bid - 1024) * 256 + threadIdx.x; i < ER * D_IN; i += 128 * 256) {
            g_lah[i] = __float2half_rn(lora_A[i]);
            int o = i >> 6, j = i & 63;
            g_lbth[(size_t)o * ER2 + j] =
                __float2half_rn(lora_B[((size_t)(j >> 4) * D_OUTD + o) * RK + (j & 15)]);
        }
    } else {
        // ---- conv_w: w_base fp32 -> g_wh half ----
        const int total = D_OUTD * D_IN / 4;
        for (int i = (bid - 1152) * 256 + threadIdx.x; i < total; i += 1024 * 256) {
            float4 v = ((const float4*)w_base)[i];
            __half2 h[2];
            h[0] = __floats2half2_rn(v.x, v.y);
            h[1] = __floats2half2_rn(v.z, v.w);
            *(uint2*)&g_wh[(size_t)i * 4] = *(uint2*)h;
        }
    }
}

// ================= prep2: h_gemm only (256 blocks, BM=32) =================
#define HSTG 3
#define HA_BYTES (32*64*2)               // 4096
#define HB_BYTES (64*64*2)               // 8192
#define HSTAGE_BYTES (HA_BYTES + HB_BYTES)  // 12288
#define HBK 64
__global__ __launch_bounds__(256) void prep2(void) {
    __shared__ __align__(1024) char smem[HSTG * HSTAGE_BYTES];   // 36 KB
    uint32_t sb = smem_u32(smem);
    int tid = threadIdx.x;
    int warp = tid >> 5, lane = tid & 31;
    int wm = warp >> 2;
    int wn = warp & 3;
    int r = lane >> 2, cq = lane & 3;
    int m0 = blockIdx.x * 32;

    const __half* abase = g_xh + (size_t)m0 * D_IN;
    const __half* bbase = g_lah;

    float acc[2][4];
    #pragma unroll
    for (int j = 0; j < 2; j++)
        #pragma unroll
        for (int k = 0; k < 4; k++) acc[j][k] = 0.f;

    auto load_h = [&](uint32_t base, const __half* ap, const __half* bp) {
        {
            int row = tid >> 3, g = tid & 7;
            CP_ASYNC16(base + row * 128 + ((g ^ (row & 7)) * 16), ap + (size_t)row * D_IN + g * 8);
        }
        #pragma unroll
        for (int i = 0; i < 2; i++) {
            int idx = i * 256 + tid;
            int row = idx >> 3, g = idx & 7;
            CP_ASYNC16(base + HA_BYTES + row * 128 + ((g ^ (row & 7)) * 16), bp + (size_t)row * D_IN + g * 8);
        }
        CP_COMMIT();
    };

    #pragma unroll
    for (int p = 0; p < HSTG - 1; p++)
        load_h(sb + p * HSTAGE_BYTES, abase + p * HBK, bbase + p * HBK);

    int ksel = lane >> 4, swm = lane & 7, rowl = lane & 15;
    const int NIT = D_IN / 64;
    int sc = 0, sn = HSTG - 1;
    for (int it = 0; it < NIT; it++) {
        CP_WAIT1();
        __syncthreads();
        int nxt = it + HSTG - 1;
        if (nxt < NIT) {
            load_h(sb + sn * HSTAGE_BYTES, abase + nxt * HBK, bbase + nxt * HBK);
            sn = (sn + 1 == HSTG) ? 0 : sn + 1;
        } else CP_COMMIT();

        uint32_t st = sb + sc * HSTAGE_BYTES;
        sc = (sc + 1 == HSTG) ? 0 : sc + 1;
        uint32_t aRow = st + (wm * 16 + rowl) * 128;
        uint32_t bRow = st + HA_BYTES + (wn * 16 + rowl) * 128;

        #pragma unroll
        for (int ks = 0; ks < 4; ks++) {
            uint32_t ko = (uint32_t)(((ks * 2 + ksel) ^ swm) * 16);
            uint32_t a0, a1, a2, a3;
            LDSM4(a0, a1, a2, a3, aRow + ko);
            uint32_t t0, t1, t2, t3;
            LDSM4(t0, t1, t2, t3, bRow + ko);
            MMA16816(acc[0][0], acc[0][1], acc[0][2], acc[0][3], a0, a1, a2, a3, t0, t2);
            MMA16816(acc[1][0], acc[1][1], acc[1][2], acc[1][3], a0, a1, a2, a3, t1, t3);
        }
    }

    #pragma unroll
    for (int h = 0; h < 2; h++) {
        int m = m0 + wm * 16 + r + h * 8;
        float gs = g_gate[m * 4 + wn] * SCALING;
        #pragma unroll
        for (int nt = 0; nt < 2; nt++) {
            int n = wn * 16 + nt * 8 + cq * 2;
            __half2 v = __floats2half2_rn(acc[nt][h * 2 + 0] * gs,
                                          acc[nt][h * 2 + 1] * gs);
            *(__half2*)&g_ch[(size_t)m * ER2 + n] = v;
        }
    }
}

// ---------------- Main GEMM: BK=128, 2 stages, CTA 128x256, 8 warps ----------------
static __device__ __forceinline__ void load_chunk(
    int tid, uint32_t stage_base,
    const __half* __restrict__ ap, int astride,
    const __half* __restrict__ bp, int bstride)
{
    #pragma unroll
    for (int i = 0; i < 8; i++) {
        int idx = i * 256 + tid;                 // A: 2048 slots (128 rows x 16 groups)
        int row = idx >> 4, g = idx & 15;
        CP_ASYNC16(stage_base + row * 256 + ((g ^ (row & 7)) * 16),
                   ap + (size_t)row * astride + g * 8);
    }
    uint32_t bb = stage_base + A_BYTES;
    #pragma unroll
    for (int i = 0; i < 16; i++) {
        int idx = i * 256 + tid;                 // B: 4096 slots (256 rows x 16 groups)
        int row = idx >> 4, g = idx & 15;
        CP_ASYNC16(bb + row * 256 + ((g ^ (row & 7)) * 16),
                   bp + (size_t)row * bstride + g * 8);
    }
    CP_COMMIT();
}

__global__ __launch_bounds__(256, 1) void gemm_h(
    const float* __restrict__ bias, float* __restrict__ out)
{
    extern __shared__ __align__(1024) char smem[];
    uint32_t sb = smem_u32(smem);
    int tid = threadIdx.x;
    int warp = tid >> 5, lane = tid & 31;
    int wm = warp >> 2;          // 0..1  (64 rows each)
    int wn = warp & 3;           // 0..3  (64 cols each)
    int r = lane >> 2;
    int cq = lane & 3;
    int m0 = blockIdx.y * BM;
    int n0 = blockIdx.x * BN;

    const __half* abase_main = g_xh + (size_t)m0 * D_IN;
    const __half* bbase_main = g_wh + (size_t)n0 * D_IN;
    const __half* abase_lora = g_ch + (size_t)m0 * ER2;
    const __half* bbase_lora = g_lbth + (size_t)n0 * ER2;

    float acc[4][8][4];
    #pragma unroll
    for (int i = 0; i < 4; i++)
        #pragma unroll
        for (int j = 0; j < 8; j++)
            #pragma unroll
            for (int k = 0; k < 4; k++) acc[i][j][k] = 0.f;

    // prologue: load chunk 0 into stage 0
    load_chunk(tid, sb, abase_main, D_IN, bbase_main, D_IN);

    int ksel = lane >> 4, swm = lane & 7, rowl = lane & 15;

    for (int it = 0; it < NIT_TOT; it++) {
        int s = it & 1;
        CP_WAIT0();
        __syncthreads();

        int nxt = it + 1;
        if (nxt < NIT_TOT) {
            uint32_t nbase = sb + (nxt & 1) * STAGE_BYTES;
            if (nxt < 32)
                load_chunk(tid, nbase,
                           abase_main + nxt * BK, D_IN, bbase_main + nxt * BK, D_IN);
            else
                load_chunk(tid, nbase, abase_lora, ER2, bbase_lora, ER2);
        }

        uint32_t st = sb + s * STAGE_BYTES;
        uint32_t aRow = st + (wm * 64 + rowl) * 256;
        uint32_t bRow = st + A_BYTES + (wn * 64 + rowl) * 256;

        #pragma unroll
        for (int ks = 0; ks < 8; ks++) {
            uint32_t ko = (uint32_t)(((ks * 2 + ksel) ^ swm) * 16);
            uint32_t afr[4][4];
            #pragma unroll
            for (int mt = 0; mt < 4; mt++)
                LDSM4(afr[mt][0], afr[mt][1], afr[mt][2], afr[mt][3],
                      aRow + mt * 4096 + ko);
            uint32_t bfr[8][2];
            #pragma unroll
            for (int ng = 0; ng < 4; ng++) {
                uint32_t t0, t1, t2, t3;
                LDSM4(t0, t1, t2, t3, bRow + ng * 4096 + ko);
                bfr[2*ng+0][0] = t0; bfr[2*ng+0][1] = t2;
                bfr[2*ng+1][0] = t1; bfr[2*ng+1][1] = t3;
            }
            #pragma unroll
            for (int mt = 0; mt < 4; mt++)
                #pragma unroll
                for (int nt = 0; nt < 8; nt++)
                    MMA16816(acc[mt][nt][0], acc[mt][nt][1], acc[mt][nt][2], acc[mt][nt][3],
                             afr[mt][0], afr[mt][1], afr[mt][2], afr[mt][3],
                             bfr[nt][0], bfr[nt][1]);
        }
    }

    // epilogue: bias + store
    #pragma unroll
    for (int mt = 0; mt < 4; mt++) {
        int mA = m0 + wm * 64 + mt * 16 + r;
        #pragma unroll
        for (int h = 0; h < 2; h++) {
            int m = mA + h * 8;
            float* orow = out + (size_t)m * D_OUTD + n0 + wn * 64;
            #pragma unroll
            for (int nt = 0; nt < 8; nt++) {
                int n = n0 + wn * 64 + nt * 8 + cq * 2;
                float2 bv = *(const float2*)&bias[n];
                float2 v;
                v.x = acc[mt][nt][h * 2 + 0] + bv.x;
                v.y = acc[mt][nt][h * 2 + 1] + bv.y;
                *(float2*)&orow[nt * 8 + cq * 2] = v;
            }
        }
    }
}

// ---------------- launch ----------------
extern "C" void kernel_launch(void* const* d_in, const int* in_sizes, int n_in,
                              void* d_out, int out_size) {
    const float* x      = (const float*)d_in[0];
    const float* w_base = (const float*)d_in[1];
    const float* b_base = (const float*)d_in[2];
    const float* w_ri   = (const float*)d_in[3];
    const float* b_ri   = (const float*)d_in[4];
    const float* w_rt   = (const float*)d_in[5];
    const float* b_rt   = (const float*)d_in[6];
    const float* lora_A = (const float*)d_in[7];
    const float* lora_B = (const float*)d_in[8];
    float* out = (float*)d_out;

    cudaFuncSetAttribute(gemm_h, cudaFuncAttributeMaxDynamicSharedMemorySize, SMEM_TOTAL);

    prep1<<<2176, 256>>>(x, w_ri, b_ri, w_rt, b_rt, lora_A, lora_B, w_base);
    prep2<<<M_TOK / 32, 256>>>();

    dim3 grid(D_OUTD / BN, M_TOK / BM);   // 16 x 64
    gemm_h<<<grid, 256, SMEM_TOTAL>>>(b_base, out);
}

// round 16
// speedup vs baseline: 1.0095x; 1.0095x over previous
#include <cuda_runtime.h>
#include <cuda_fp16.h>
#include <cstdint>
#include <math.h>

#define S_LEN   2048
#define D_IN    4096
#define D_OUTD  4096
#define M_TOK   8192
#define RK      16
#define ER      64
#define SCALING 2.0f

// ---- main fp16 mma gemm config: CTA 128x256, 8 warps, warp 64x64, BK=128, 2 stages ----
#define BM      128
#define BN      256
#define BK      128
#define NIT_MAIN 32                      // 4096/128
#define A_BYTES (BM*BK*2)                // 32768
#define B_BYTES (BN*BK*2)                // 65536
#define STAGE_BYTES (A_BYTES + B_BYTES)  // 98304
#define SMEM_TOTAL (2*STAGE_BYTES)       // 196608

// ---------------- scratch (half copies) ----------------
__device__ __align__(1024) __half g_xh[M_TOK * D_IN];     // 67 MB
__device__ __align__(1024) __half g_wh[D_OUTD * D_IN];    // 33.5 MB
__device__ __align__(1024) __half g_lah[ER * D_IN];       // lora_A half [er][k]
__device__ __align__(1024) __half g_ch[M_TOK * ER];       // gate-scaled h (half)
__device__ __align__(1024) __half g_lbth[D_OUTD * ER];    // lora_B re-laid [o][er]
__device__ float g_gate[M_TOK * 4];

// ---------------- helpers ----------------
static __device__ __forceinline__ uint32_t smem_u32(const void* p) {
    uint32_t a;
    asm("{ .reg .u64 t; cvta.to.shared.u64 t, %1; cvt.u32.u64 %0, t; }" : "=r"(a) : "l"(p));
    return a;
}
#define CP_ASYNC16(dst, src) \
    asm volatile("cp.async.cg.shared.global [%0], [%1], 16;" :: "r"(dst), "l"(src) : "memory")
#define CP_COMMIT() asm volatile("cp.async.commit_group;" ::: "memory")
#define CP_WAIT0()  asm volatile("cp.async.wait_group 0;" ::: "memory")
#define CP_WAIT1()  asm volatile("cp.async.wait_group 1;" ::: "memory")

#define LDSM4(r0, r1, r2, r3, a) \
    asm volatile("ldmatrix.sync.aligned.m8n8.x4.shared.b16 {%0,%1,%2,%3}, [%4];" \
        : "=r"(r0), "=r"(r1), "=r"(r2), "=r"(r3) : "r"(a))

#define MMA16816(c0, c1, c2, c3, a0, a1, a2, a3, b0, b1) \
    asm volatile("mma.sync.aligned.m16n8k16.row.col.f32.f16.f16.f32 " \
        "{%0,%1,%2,%3}, {%4,%5,%6,%7}, {%8,%9}, {%0,%1,%2,%3};" \
        : "+f"(c0), "+f"(c1), "+f"(c2), "+f"(c3) \
        : "r"(a0), "r"(a1), "r"(a2), "r"(a3), "r"(b0), "r"(b1))

// ================= prep1: conv_xg (blocks 0..1023) || conv_small (1024..1151) ==========
__global__ __launch_bounds__(256) void prep1(
    const float* __restrict__ x,
    const float* __restrict__ w_img, const float* __restrict__ b_img,
    const float* __restrict__ w_txt, const float* __restrict__ b_txt,
    const float* __restrict__ lora_A, const float* __restrict__ lora_B)
{
    int bid = blockIdx.x;
    if (bid < 1024) {
        // ---- conv_x + router gate: one warp per token (proven 39-reg form) ----
        int warp = threadIdx.x >> 5, lane = threadIdx.x & 31;
        int t = bid * 8 + warp;
        int s = t & (S_LEN - 1);
        const float* wr = (s < 32) ? w_img : w_txt;
        const float* br = (s < 32) ? b_img : b_txt;
        const float* xp = x + (size_t)t * D_IN;
        __half* xh = g_xh + (size_t)t * D_IN;

        float a0 = 0.f, a1 = 0.f, a2 = 0.f, a3 = 0.f;
        #pragma unroll 8
        for (int itc = 0; itc < 32; itc++) {
            int k = lane * 4 + itc * 128;
            float4 v = *(const float4*)(xp + k);
            __half2 h[2];
            h[0] = __floats2half2_rn(v.x, v.y);
            h[1] = __floats2half2_rn(v.z, v.w);
            *(uint2*)(xh + k) = *(uint2*)h;
            float4 w0 = *(const float4*)(wr + k);
            float4 w1 = *(const float4*)(wr + D_IN + k);
            float4 w2 = *(const float4*)(wr + 2 * D_IN + k);
            float4 w3 = *(const float4*)(wr + 3 * D_IN + k);
            a0 = fmaf(v.x, w0.x, fmaf(v.y, w0.y, fmaf(v.z, w0.z, fmaf(v.w, w0.w, a0))));
            a1 = fmaf(v.x, w1.x, fmaf(v.y, w1.y, fmaf(v.z, w1.z, fmaf(v.w, w1.w, a1))));
            a2 = fmaf(v.x, w2.x, fmaf(v.y, w2.y, fmaf(v.z, w2.z, fmaf(v.w, w2.w, a2))));
            a3 = fmaf(v.x, w3.x, fmaf(v.y, w3.y, fmaf(v.z, w3.z, fmaf(v.w, w3.w, a3))));
        }
        #pragma unroll
        for (int off = 16; off; off >>= 1) {
            a0 += __shfl_down_sync(0xffffffffu, a0, off);
            a1 += __shfl_down_sync(0xffffffffu, a1, off);
            a2 += __shfl_down_sync(0xffffffffu, a2, off);
            a3 += __shfl_down_sync(0xffffffffu, a3, off);
        }
        if (lane == 0) {
            float l0 = a0 + br[0], l1 = a1 + br[1], l2 = a2 + br[2], l3 = a3 + br[3];
            float mx = fmaxf(fmaxf(l0, l1), fmaxf(l2, l3));
            float e0 = expf(l0 - mx), e1 = expf(l1 - mx), e2 = expf(l2 - mx), e3 = expf(l3 - mx);
            float inv = 1.0f / (e0 + e1 + e2 + e3);
            g_gate[t * 4 + 0] = e0 * inv; g_gate[t * 4 + 1] = e1 * inv;
            g_gate[t * 4 + 2] = e2 * inv; g_gate[t * 4 + 3] = e3 * inv;
        }
    } else {
        // ---- conv_small: lora_A -> half, lora_B -> transposed half (ER stride) ----
        for (int i = (bid - 1024) * 256 + threadIdx.x; i < ER * D_IN; i += 128 * 256) {
            g_lah[i] = __float2half_rn(lora_A[i]);
            int o = i >> 6, j = i & 63;
            g_lbth[i] = __float2half_rn(lora_B[((size_t)(j >> 4) * D_OUTD + o) * RK + (j & 15)]);
        }
    }
}

// ================= prep2: h_gemm (blocks 0..255, BM=32) || conv_w (256..1279) ==========
#define HSTG 3
#define HA_BYTES (32*64*2)               // 4096
#define HB_BYTES (64*64*2)               // 8192
#define HSTAGE_BYTES (HA_BYTES + HB_BYTES)  // 12288
#define HBK 64
__global__ __launch_bounds__(256) void prep2(const float* __restrict__ w) {
    __shared__ __align__(1024) char smem[HSTG * HSTAGE_BYTES];   // 36 KB
    int bid = blockIdx.x;
    if (bid >= 256) {
        // ---- conv_w: w_base fp32 -> g_wh half, grid-stride over float4s ----
        const int total = D_OUTD * D_IN / 4;
        for (int i = (bid - 256) * 256 + threadIdx.x; i < total; i += 1024 * 256) {
            float4 v = ((const float4*)w)[i];
            __half2 h[2];
            h[0] = __floats2half2_rn(v.x, v.y);
            h[1] = __floats2half2_rn(v.z, v.w);
            *(uint2*)&g_wh[(size_t)i * 4] = *(uint2*)h;
        }
        return;
    }
    // ---- h-GEMM tile: g_ch[m0..m0+31] = half((g_xh @ g_lah^T) * gate * SCALING) ----
    uint32_t sb = smem_u32(smem);
    int tid = threadIdx.x;
    int warp = tid >> 5, lane = tid & 31;
    int wm = warp >> 2;
    int wn = warp & 3;
    int r = lane >> 2, cq = lane & 3;
    int m0 = bid * 32;

    const __half* abase = g_xh + (size_t)m0 * D_IN;
    const __half* bbase = g_lah;

    float acc[2][4];
    #pragma unroll
    for (int j = 0; j < 2; j++)
        #pragma unroll
        for (int k = 0; k < 4; k++) acc[j][k] = 0.f;

    auto load_h = [&](uint32_t base, const __half* ap, const __half* bp) {
        {
            int row = tid >> 3, g = tid & 7;
            CP_ASYNC16(base + row * 128 + ((g ^ (row & 7)) * 16), ap + (size_t)row * D_IN + g * 8);
        }
        #pragma unroll
        for (int i = 0; i < 2; i++) {
            int idx = i * 256 + tid;
            int row = idx >> 3, g = idx & 7;
            CP_ASYNC16(base + HA_BYTES + row * 128 + ((g ^ (row & 7)) * 16), bp + (size_t)row * D_IN + g * 8);
        }
        CP_COMMIT();
    };

    #pragma unroll
    for (int p = 0; p < HSTG - 1; p++)
        load_h(sb + p * HSTAGE_BYTES, abase + p * HBK, bbase + p * HBK);

    int ksel = lane >> 4, swm = lane & 7, rowl = lane & 15;
    const int NIT = D_IN / 64;
    int sc = 0, sn = HSTG - 1;
    for (int it = 0; it < NIT; it++) {
        CP_WAIT1();
        __syncthreads();
        int nxt = it + HSTG - 1;
        if (nxt < NIT) {
            load_h(sb + sn * HSTAGE_BYTES, abase + nxt * HBK, bbase + nxt * HBK);
            sn = (sn + 1 == HSTG) ? 0 : sn + 1;
        } else CP_COMMIT();

        uint32_t st = sb + sc * HSTAGE_BYTES;
        sc = (sc + 1 == HSTG) ? 0 : sc + 1;
        uint32_t aRow = st + (wm * 16 + rowl) * 128;
        uint32_t bRow = st + HA_BYTES + (wn * 16 + rowl) * 128;

        #pragma unroll
        for (int ks = 0; ks < 4; ks++) {
            uint32_t ko = (uint32_t)(((ks * 2 + ksel) ^ swm) * 16);
            uint32_t a0, a1, a2, a3;
            LDSM4(a0, a1, a2, a3, aRow + ko);
            uint32_t t0, t1, t2, t3;
            LDSM4(t0, t1, t2, t3, bRow + ko);
            MMA16816(acc[0][0], acc[0][1], acc[0][2], acc[0][3], a0, a1, a2, a3, t0, t2);
            MMA16816(acc[1][0], acc[1][1], acc[1][2], acc[1][3], a0, a1, a2, a3, t1, t3);
        }
    }

    #pragma unroll
    for (int h = 0; h < 2; h++) {
        int m = m0 + wm * 16 + r + h * 8;
        float gs = g_gate[m * 4 + wn] * SCALING;
        #pragma unroll
        for (int nt = 0; nt < 2; nt++) {
            int n = wn * 16 + nt * 8 + cq * 2;
            __half2 v = __floats2half2_rn(acc[nt][h * 2 + 0] * gs,
                                          acc[nt][h * 2 + 1] * gs);
            *(__half2*)&g_ch[(size_t)m * ER + n] = v;
        }
    }
}

// ---------------- Main GEMM: BK=128 x32 chunks + compact K=64 LoRA tail ----------------
static __device__ __forceinline__ void load_chunk(
    int tid, uint32_t stage_base,
    const __half* __restrict__ ap, const __half* __restrict__ bp)
{
    #pragma unroll
    for (int i = 0; i < 8; i++) {
        int idx = i * 256 + tid;                 // A: 2048 slots (128 rows x 16 groups)
        int row = idx >> 4, g = idx & 15;
        CP_ASYNC16(stage_base + row * 256 + ((g ^ (row & 7)) * 16),
                   ap + (size_t)row * D_IN + g * 8);
    }
    uint32_t bb = stage_base + A_BYTES;
    #pragma unroll
    for (int i = 0; i < 16; i++) {
        int idx = i * 256 + tid;                 // B: 4096 slots (256 rows x 16 groups)
        int row = idx >> 4, g = idx & 15;
        CP_ASYNC16(bb + row * 256 + ((g ^ (row & 7)) * 16),
                   bp + (size_t)row * D_IN + g * 8);
    }
    CP_COMMIT();
}

// compact LoRA chunk: K=64, 128-byte rows
static __device__ __forceinline__ void load_lora(
    int tid, uint32_t stage_base,
    const __half* __restrict__ ap, const __half* __restrict__ bp)
{
    #pragma unroll
    for (int i = 0; i < 4; i++) {
        int idx = i * 256 + tid;                 // A: 1024 slots (128 rows x 8 groups)
        int row = idx >> 3, g = idx & 7;
        CP_ASYNC16(stage_base + row * 128 + ((g ^ (row & 7)) * 16),
                   ap + (size_t)row * ER + g * 8);
    }
    uint32_t bb = stage_base + A_BYTES;
    #pragma unroll
    for (int i = 0; i < 8; i++) {
        int idx = i * 256 + tid;                 // B: 2048 slots (256 rows x 8 groups)
        int row = idx >> 3, g = idx & 7;
        CP_ASYNC16(bb + row * 128 + ((g ^ (row & 7)) * 16),
                   bp + (size_t)row * ER + g * 8);
    }
    CP_COMMIT();
}

__global__ __launch_bounds__(256, 1) void gemm_h(
    const float* __restrict__ bias, float* __restrict__ out)
{
    extern __shared__ __align__(1024) char smem[];
    uint32_t sb = smem_u32(smem);
    int tid = threadIdx.x;
    int warp = tid >> 5, lane = tid & 31;
    int wm = warp >> 2;          // 0..1  (64 rows each)
    int wn = warp & 3;           // 0..3  (64 cols each)
    int r = lane >> 2;
    int cq = lane & 3;
    int m0 = blockIdx.y * BM;
    int n0 = blockIdx.x * BN;

    const __half* abase_main = g_xh + (size_t)m0 * D_IN;
    const __half* bbase_main = g_wh + (size_t)n0 * D_IN;
    const __half* abase_lora = g_ch + (size_t)m0 * ER;
    const __half* bbase_lora = g_lbth + (size_t)n0 * ER;

    float acc[4][8][4];
    #pragma unroll
    for (int i = 0; i < 4; i++)
        #pragma unroll
        for (int j = 0; j < 8; j++)
            #pragma unroll
            for (int k = 0; k < 4; k++) acc[i][j][k] = 0.f;

    // prologue: load chunk 0 into stage 0
    load_chunk(tid, sb, abase_main, bbase_main);

    int ksel = lane >> 4, swm = lane & 7, rowl = lane & 15;

    for (int it = 0; it < NIT_MAIN; it++) {
        int s = it & 1;
        CP_WAIT0();
        __syncthreads();

        int nxt = it + 1;
        uint32_t nbase = sb + (nxt & 1) * STAGE_BYTES;
        if (nxt < NIT_MAIN)
            load_chunk(tid, nbase, abase_main + nxt * BK, bbase_main + nxt * BK);
        else
            load_lora(tid, nbase, abase_lora, bbase_lora);

        uint32_t st = sb + s * STAGE_BYTES;
        uint32_t aRow = st + (wm * 64 + rowl) * 256;
        uint32_t bRow = st + A_BYTES + (wn * 64 + rowl) * 256;

        #pragma unroll
        for (int ks = 0; ks < 8; ks++) {
            uint32_t ko = (uint32_t)(((ks * 2 + ksel) ^ swm) * 16);
            uint32_t afr[4][4];
            #pragma unroll
            for (int mt = 0; mt < 4; mt++)
                LDSM4(afr[mt][0], afr[mt][1], afr[mt][2], afr[mt][3],
                      aRow + mt * 4096 + ko);
            uint32_t bfr[8][2];
            #pragma unroll
            for (int ng = 0; ng < 4; ng++) {
                uint32_t t0, t1, t2, t3;
                LDSM4(t0, t1, t2, t3, bRow + ng * 4096 + ko);
                bfr[2*ng+0][0] = t0; bfr[2*ng+0][1] = t2;
                bfr[2*ng+1][0] = t1; bfr[2*ng+1][1] = t3;
            }
            #pragma unroll
            for (int mt = 0; mt < 4; mt++)
                #pragma unroll
                for (int nt = 0; nt < 8; nt++)
                    MMA16816(acc[mt][nt][0], acc[mt][nt][1], acc[mt][nt][2], acc[mt][nt][3],
                             afr[mt][0], afr[mt][1], afr[mt][2], afr[mt][3],
                             bfr[nt][0], bfr[nt][1]);
        }
    }

    // ---- LoRA tail: K=64 compact chunk in stage (NIT_MAIN & 1) == 0 ----
    {
        CP_WAIT0();
        __syncthreads();
        uint32_t st = sb;                       // stage 0
        uint32_t aRow = st + (wm * 64 + rowl) * 128;
        uint32_t bRow = st + A_BYTES + (wn * 64 + rowl) * 128;

        #pragma unroll
        for (int ks = 0; ks < 4; ks++) {
            uint32_t ko = (uint32_t)(((ks * 2 + ksel) ^ swm) * 16);
            uint32_t afr[4][4];
            #pragma unroll
            for (int mt = 0; mt < 4; mt++)
                LDSM4(afr[mt][0], afr[mt][1], afr[mt][2], afr[mt][3],
                      aRow + mt * 2048 + ko);
            uint32_t bfr[8][2];
            #pragma unroll
            for (int ng = 0; ng < 4; ng++) {
                uint32_t t0, t1, t2, t3;
                LDSM4(t0, t1, t2, t3, bRow + ng * 2048 + ko);
                bfr[2*ng+0][0] = t0; bfr[2*ng+0][1] = t2;
                bfr[2*ng+1][0] = t1; bfr[2*ng+1][1] = t3;
            }
            #pragma unroll
            for (int mt = 0; mt < 4; mt++)
                #pragma unroll
                for (int nt = 0; nt < 8; nt++)
                    MMA16816(acc[mt][nt][0], acc[mt][nt][1], acc[mt][nt][2], acc[mt][nt][3],
                             afr[mt][0], afr[mt][1], afr[mt][2], afr[mt][3],
                             bfr[nt][0], bfr[nt][1]);
        }
    }

    // epilogue: bias + store
    #pragma unroll
    for (int mt = 0; mt < 4; mt++) {
        int mA = m0 + wm * 64 + mt * 16 + r;
        #pragma unroll
        for (int h = 0; h < 2; h++) {
            int m = mA + h * 8;
            float* orow = out + (size_t)m * D_OUTD + n0 + wn * 64;
            #pragma unroll
            for (int nt = 0; nt < 8; nt++) {
                int n = n0 + wn * 64 + nt * 8 + cq * 2;
                float2 bv = *(const float2*)&bias[n];
                float2 v;
                v.x = acc[mt][nt][h * 2 + 0] + bv.x;
                v.y = acc[mt][nt][h * 2 + 1] + bv.y;
                *(float2*)&orow[nt * 8 + cq * 2] = v;
            }
        }
    }
}

// ---------------- launch ----------------
extern "C" void kernel_launch(void* const* d_in, const int* in_sizes, int n_in,
                              void* d_out, int out_size) {
    const float* x      = (const float*)d_in[0];
    const float* w_base = (const float*)d_in[1];
    const float* b_base = (const float*)d_in[2];
    const float* w_ri   = (const float*)d_in[3];
    const float* b_ri   = (const float*)d_in[4];
    const float* w_rt   = (const float*)d_in[5];
    const float* b_rt   = (const float*)d_in[6];
    const float* lora_A = (const float*)d_in[7];
    const float* lora_B = (const float*)d_in[8];
    float* out = (float*)d_out;

    cudaFuncSetAttribute(gemm_h, cudaFuncAttributeMaxDynamicSharedMemorySize, SMEM_TOTAL);

    prep1<<<1152, 256>>>(x, w_ri, b_ri, w_rt, b_rt, lora_A, lora_B);
    prep2<<<1280, 256>>>(w_base);

    dim3 grid(D_OUTD / BN, M_TOK / BM);   // 16 x 64
    gemm_h<<<grid, 256, SMEM_TOTAL>>>(b_base, out);
}